// round 1
// baseline (speedup 1.0000x reference)
#include <cuda_runtime.h>

// Problem constants (fixed shapes from reference setup_inputs)
#define B_ 2048
#define I_ 2048
#define H_ 2048
#define T_ 4
#define M_ (B_ * T_)   // 8192 GEMM rows (b,t)
#define N_ (3 * H_)    // 6144 GEMM cols (3 gates)
#define K_ I_          // 2048 reduction dim

// Scratch (device globals: allocation-free)
__device__ float g_X[(size_t)M_ * K_];   // 64 MB:  transposed inputs [M, K]
__device__ float g_Y[(size_t)M_ * N_];   // 192 MB: pre-activations  [M, N]

// ---------------------------------------------------------------------------
// Kernel 1: transpose inputs [B, I, T] -> X[(b*T+t), i]
// Each thread handles one (b, i): one float4 read (T=4 contiguous), 4 scattered
// (but warp-coalesced) writes.
// ---------------------------------------------------------------------------
__global__ void transpose_kernel(const float* __restrict__ in) {
    int idx = blockIdx.x * blockDim.x + threadIdx.x;   // over B*I
    if (idx >= B_ * I_) return;
    int b = idx / I_;
    int i = idx - b * I_;
    float4 v = *(const float4*)(in + (size_t)idx * T_);
    size_t base = (size_t)(b * T_) * K_ + i;
    g_X[base + 0 * (size_t)K_] = v.x;
    g_X[base + 1 * (size_t)K_] = v.y;
    g_X[base + 2 * (size_t)K_] = v.z;
    g_X[base + 3 * (size_t)K_] = v.w;
}

// ---------------------------------------------------------------------------
// Kernel 2: SGEMM  Y[m,n] = sum_k X[m,k] * W[n,k]   (both K-major)
// 128x128 block tile, BK=8, 8x8 per-thread micro-tile, 256 threads,
// double-buffered shared memory.
// ---------------------------------------------------------------------------
#define BM 128
#define BN 128
#define BK 8
#define NKT (K_ / BK)

__global__ __launch_bounds__(256) void sgemm_kernel(const float* __restrict__ W) {
    __shared__ float As[2][BK][BM];
    __shared__ float Bs[2][BK][BN];

    const int tid = threadIdx.x;
    const int bx = blockIdx.x;           // N tile index
    const int by = blockIdx.y;           // M tile index
    const int tx = tid & 15;             // 0..15 -> 8 cols each
    const int ty = tid >> 4;             // 0..15 -> 8 rows each

    // Global-load mapping: each thread loads one float4 of A and one of B per
    // k-tile. 256 threads * 4 floats = 1024 = 128 rows x 8 k.
    const int loadRow = tid >> 1;        // 0..127
    const int loadK   = (tid & 1) * 4;   // 0 or 4

    const float* Aptr = g_X + (size_t)(by * BM + loadRow) * K_ + loadK;
    const float* Bptr = W   + (size_t)(bx * BN + loadRow) * K_ + loadK;

    float acc[8][8] = {};

    // Preload tile 0
    float4 aReg = *(const float4*)(Aptr);
    float4 bReg = *(const float4*)(Bptr);
    {
        const float* av = (const float*)&aReg;
        const float* bv = (const float*)&bReg;
#pragma unroll
        for (int i = 0; i < 4; i++) {
            As[0][loadK + i][loadRow] = av[i];
            Bs[0][loadK + i][loadRow] = bv[i];
        }
    }
    __syncthreads();

    int buf = 0;
#pragma unroll 1
    for (int kt = 0; kt < NKT; ++kt) {
        // Prefetch next tile from global while computing current one
        if (kt + 1 < NKT) {
            aReg = *(const float4*)(Aptr + (size_t)(kt + 1) * BK);
            bReg = *(const float4*)(Bptr + (size_t)(kt + 1) * BK);
        }

#pragma unroll
        for (int kk = 0; kk < BK; ++kk) {
            float a[8], b[8];
            float4 a0 = *(const float4*)&As[buf][kk][ty * 8];
            float4 a1 = *(const float4*)&As[buf][kk][ty * 8 + 4];
            float4 b0 = *(const float4*)&Bs[buf][kk][tx * 8];
            float4 b1 = *(const float4*)&Bs[buf][kk][tx * 8 + 4];
            a[0]=a0.x; a[1]=a0.y; a[2]=a0.z; a[3]=a0.w;
            a[4]=a1.x; a[5]=a1.y; a[6]=a1.z; a[7]=a1.w;
            b[0]=b0.x; b[1]=b0.y; b[2]=b0.z; b[3]=b0.w;
            b[4]=b1.x; b[5]=b1.y; b[6]=b1.z; b[7]=b1.w;
#pragma unroll
            for (int i = 0; i < 8; i++)
#pragma unroll
                for (int j = 0; j < 8; j++)
                    acc[i][j] += a[i] * b[j];
        }

        if (kt + 1 < NKT) {
            int nb = buf ^ 1;
            const float* av = (const float*)&aReg;
            const float* bv = (const float*)&bReg;
#pragma unroll
            for (int i = 0; i < 4; i++) {
                As[nb][loadK + i][loadRow] = av[i];
                Bs[nb][loadK + i][loadRow] = bv[i];
            }
            __syncthreads();
            buf = nb;
        }
    }

    // Store 8x8 tile (float4 vectorized)
#pragma unroll
    for (int i = 0; i < 8; i++) {
        float* crow = g_Y + (size_t)(by * BM + ty * 8 + i) * N_ + bx * BN + tx * 8;
        *(float4*)(crow)     = make_float4(acc[i][0], acc[i][1], acc[i][2], acc[i][3]);
        *(float4*)(crow + 4) = make_float4(acc[i][4], acc[i][5], acc[i][6], acc[i][7]);
    }
}

// ---------------------------------------------------------------------------
// Kernel 3: gates + LIF. One thread per (b, j).
//   r = (Y_r + b_ih_r + b_hh_r) > 0
//   z = (Y_z + b_ih_z + b_hh_z) > 0
//   n = (Y_n + b_ih_n + r*b_hh_n) > 0
//   h = (1 - z) * n
//   LIF: reset = (mem-1 > 0); mem = 0.99*mem + h - reset; spk = (mem-1 > 0)
// Output layout [B, H, T] -> one float4 store per thread.
// ---------------------------------------------------------------------------
__global__ void lif_kernel(const float* __restrict__ bih,
                           const float* __restrict__ bhh,
                           float* __restrict__ out) {
    int idx = blockIdx.x * blockDim.x + threadIdx.x;   // over B*H
    if (idx >= B_ * H_) return;
    int b = idx / H_;
    int j = idx - b * H_;

    float bihr = bih[j], bihz = bih[j + H_], bihn = bih[j + 2 * H_];
    float bhhr = bhh[j], bhhz = bhh[j + H_], bhhn = bhh[j + 2 * H_];

    float mem = 0.0f;
    float4 spk4;
    float* sp = &spk4.x;

#pragma unroll
    for (int t = 0; t < T_; t++) {
        const float* yrow = g_Y + (size_t)(b * T_ + t) * N_;
        float gr = (yrow[j] + bihr) + bhhr;
        float gz = (yrow[j + H_] + bihz) + bhhz;
        float r  = gr > 0.0f ? 1.0f : 0.0f;
        float gn = (yrow[j + 2 * H_] + bihn) + r * bhhn;
        float z  = gz > 0.0f ? 1.0f : 0.0f;
        float n  = gn > 0.0f ? 1.0f : 0.0f;
        float h  = (1.0f - z) * n;

        float reset = (mem - 1.0f) > 0.0f ? 1.0f : 0.0f;
        mem = 0.99f * mem + h - reset * 1.0f;
        sp[t] = (mem - 1.0f) > 0.0f ? 1.0f : 0.0f;
    }

    *(float4*)(out + (size_t)idx * T_) = spk4;
}

// ---------------------------------------------------------------------------
extern "C" void kernel_launch(void* const* d_in, const int* in_sizes, int n_in,
                              void* d_out, int out_size) {
    const float* inp = (const float*)d_in[0];   // inputs [B, I, T]
    const float* Wih = (const float*)d_in[1];   // [3H, I]
    const float* bih = (const float*)d_in[2];   // [3H]
    // d_in[3] = W_hh is mathematically unused (h0 == 0)
    const float* bhh = (const float*)d_in[4];   // [3H]
    float* out = (float*)d_out;                 // [B, H, T]

    transpose_kernel<<<(B_ * I_ + 255) / 256, 256>>>(inp);

    dim3 grid(N_ / BN, M_ / BM);   // (48, 64)
    sgemm_kernel<<<grid, 256>>>(Wih);

    lif_kernel<<<(B_ * H_ + 255) / 256, 256>>>(bih, bhh, out);
}

// round 3
// speedup vs baseline: 2.9524x; 2.9524x over previous
#include <cuda_runtime.h>
#include <cuda_fp16.h>
#include <cstdint>

// ---------------------------------------------------------------------------
// Problem constants
// ---------------------------------------------------------------------------
#define B_ 2048
#define I_ 2048
#define H_ 2048
#define T_ 4
#define M_ (B_ * T_)   // 8192
#define N_ (3 * H_)    // 6144
#define K_ I_          // 2048

#define DELTA 1e-4f
#define FIXCAP (1u << 20)

// Scratch (device globals: allocation-free)
__device__ float  g_Xf[(size_t)M_ * K_];          // 64 MB fp32 transposed inputs
__device__ __half g_A16[2][(size_t)M_ * K_];      // 2 x 32 MB fp16 splits of X
__device__ __half g_B16[2][(size_t)N_ * K_];      // 2 x 24 MB fp16 splits of W_ih
__device__ float  g_Y[(size_t)M_ * N_];           // 192 MB pre-activations
__device__ unsigned g_fix[FIXCAP];
__device__ unsigned g_nfix;

// ---------------------------------------------------------------------------
// Helpers
// ---------------------------------------------------------------------------
__device__ __forceinline__ uint32_t smem_u32(const void* p) {
    uint32_t a;
    asm("{ .reg .u64 t; cvta.to.shared.u64 t, %1; cvt.u32.u64 %0, t; }" : "=r"(a) : "l"(p));
    return a;
}
#define SWZ128(o) ((o) ^ (((o) >> 3) & 0x70))

__device__ __forceinline__ void cp_async16(uint32_t s, const void* g) {
    asm volatile("cp.async.cg.shared.global [%0], [%1], 16;" :: "r"(s), "l"(g));
}
#define CP_COMMIT() asm volatile("cp.async.commit_group;" ::: "memory")
#define CP_WAIT(n)  asm volatile("cp.async.wait_group %0;" :: "n"(n) : "memory")

#define LDSM4(r0, r1, r2, r3, addr)                                              \
    asm volatile("ldmatrix.sync.aligned.m8n8.x4.shared.b16 {%0,%1,%2,%3}, [%4];" \
                 : "=r"(r0), "=r"(r1), "=r"(r2), "=r"(r3) : "r"(addr))

#define MMA16816(d, a, b)                                                        \
    asm volatile("mma.sync.aligned.m16n8k16.row.col.f32.f16.f16.f32 "            \
                 "{%0,%1,%2,%3}, {%4,%5,%6,%7}, {%8,%9}, {%0,%1,%2,%3};"         \
                 : "+f"((d)[0]), "+f"((d)[1]), "+f"((d)[2]), "+f"((d)[3])        \
                 : "r"((a)[0]), "r"((a)[1]), "r"((a)[2]), "r"((a)[3]),           \
                   "r"((b)[0]), "r"((b)[1]))

// ---------------------------------------------------------------------------
// zero fixup counter (runs first every launch/replay)
// ---------------------------------------------------------------------------
__global__ void zero_fix_kernel() { g_nfix = 0u; }

// ---------------------------------------------------------------------------
// Prep: transpose inputs -> fp32 X + fp16 hi/lo splits; split W
// ---------------------------------------------------------------------------
__global__ void prep_A(const float* __restrict__ in) {
    int idx = blockIdx.x * blockDim.x + threadIdx.x;   // over B*I
    if (idx >= B_ * I_) return;
    int b = idx / I_;
    int i = idx - b * I_;
    float4 v = *(const float4*)(in + (size_t)idx * T_);
    float vs[4] = {v.x, v.y, v.z, v.w};
#pragma unroll
    for (int t = 0; t < 4; t++) {
        size_t o = (size_t)(b * 4 + t) * K_ + i;
        float a = vs[t];
        g_Xf[o] = a;
        __half h0 = __float2half_rn(a);
        float r1 = a - __half2float(h0);
        g_A16[0][o] = h0;
        g_A16[1][o] = __float2half_rn(r1);
    }
}

__global__ void prep_B(const float* __restrict__ W) {
    int idx = blockIdx.x * blockDim.x + threadIdx.x;   // over N*K/4
    if (idx >= N_ * K_ / 4) return;
    float4 v = *(const float4*)(W + (size_t)idx * 4);
    float vs[4] = {v.x, v.y, v.z, v.w};
    __half o0[4], o1[4];
#pragma unroll
    for (int j = 0; j < 4; j++) {
        float a = vs[j];
        __half h0 = __float2half_rn(a);
        o0[j] = h0;
        o1[j] = __float2half_rn(a - __half2float(h0));
    }
    size_t base = (size_t)idx * 4;
    *(uint2*)&g_B16[0][base] = *(uint2*)o0;
    *(uint2*)&g_B16[1][base] = *(uint2*)o1;
}

// ---------------------------------------------------------------------------
// HMMA GEMM: Y[m,n] = X[m,:]·W[n,:], computed as a0b0 + a0b1 + a1b0 over
// an extended K of 96 chunks (3 split-pairs x 32 chunks of 64).
// CTA tile 128x128, 8 warps (2x4, warp tile 64x32), double-buffered cp.async.
// Epilogue stores Y and flags borderline gates for exact fp64 recompute.
// ---------------------------------------------------------------------------
#define NCH 96
#define STAGE_B 32768                       // 16 KB A + 16 KB B
#define SMEM_TOTAL (2 * STAGE_B)            // 64 KB

__device__ __forceinline__ void load_chunk(uint32_t sb, int stage, int c,
                                           int by, int bx, int tid) {
    const __half* srcA = g_A16[c >= 64 ? 1 : 0];
    const __half* srcB = g_B16[(c >= 32 && c < 64) ? 1 : 0];
    int kb = (c & 31) * 64;
    uint32_t sA = sb + stage * STAGE_B;
    uint32_t sB = sA + 16384;
#pragma unroll
    for (int q = 0; q < 4; ++q) {
        int sidx = tid + q * 256;      // 0..1023
        int row = sidx >> 3;
        int seg = sidx & 7;
        uint32_t off = SWZ128(row * 128 + seg * 16);
        cp_async16(sA + off, srcA + (size_t)(by * 128 + row) * K_ + kb + seg * 8);
        cp_async16(sB + off, srcB + (size_t)(bx * 128 + row) * K_ + kb + seg * 8);
    }
    CP_COMMIT();
}

__global__ __launch_bounds__(256) void gemm_kernel(const float* __restrict__ bih,
                                                   const float* __restrict__ bhh) {
    extern __shared__ __align__(128) char smem[];
    uint32_t sb = smem_u32(smem);
    const int tid = threadIdx.x;
    const int wid = tid >> 5;
    const int lid = tid & 31;
    const int bx = blockIdx.x;    // N tile (48)
    const int by = blockIdx.y;    // M tile (64)
    const int warp_m = wid >> 2;  // 0..1
    const int warp_n = wid & 3;   // 0..3

    float acc[4][4][4] = {};

    load_chunk(sb, 0, 0, by, bx, tid);

    const int grp = lid >> 3, lrow = lid & 7;

    for (int c = 0; c < NCH; ++c) {
        if (c + 1 < NCH) {
            load_chunk(sb, (c + 1) & 1, c + 1, by, bx, tid);
            CP_WAIT(1);
        } else {
            CP_WAIT(0);
        }
        __syncthreads();

        uint32_t sA = sb + (c & 1) * STAGE_B;
        uint32_t sB = sA + 16384;
#pragma unroll
        for (int ks = 0; ks < 4; ++ks) {
            uint32_t Af[4][4];
#pragma unroll
            for (int am = 0; am < 4; ++am) {
                int row = warp_m * 64 + am * 16 + (grp & 1) * 8 + lrow;
                uint32_t ad = sA + SWZ128(row * 128 + ks * 32 + (grp >> 1) * 16);
                LDSM4(Af[am][0], Af[am][1], Af[am][2], Af[am][3], ad);
            }
            uint32_t Bf[4][2];
#pragma unroll
            for (int bp = 0; bp < 2; ++bp) {
                int row = warp_n * 32 + bp * 16 + (grp >> 1) * 8 + lrow;
                uint32_t ad = sB + SWZ128(row * 128 + ks * 32 + (grp & 1) * 16);
                uint32_t r0, r1, r2, r3;
                LDSM4(r0, r1, r2, r3, ad);
                Bf[bp * 2][0] = r0; Bf[bp * 2][1] = r1;
                Bf[bp * 2 + 1][0] = r2; Bf[bp * 2 + 1][1] = r3;
            }
#pragma unroll
            for (int am = 0; am < 4; ++am)
#pragma unroll
                for (int bn = 0; bn < 4; ++bn)
                    MMA16816(acc[am][bn], Af[am], Bf[bn]);
        }
        __syncthreads();
    }

    // Epilogue: store + borderline-gate flagging
#pragma unroll
    for (int bn = 0; bn < 4; ++bn) {
        int col = bx * 128 + warp_n * 32 + bn * 8 + (lid & 3) * 2;
        float bih0 = bih[col], bih1 = bih[col + 1];
        float bhh0 = bhh[col], bhh1 = bhh[col + 1];
        int g = col >> 11;                        // 0:r 1:z 2:n
        float t2a = bih0 + bhh0, t2b = bih1 + bhh1;
        float t1a = (g == 2) ? bih0 : t2a;
        float t1b = (g == 2) ? bih1 : t2b;
#pragma unroll
        for (int am = 0; am < 4; ++am) {
            int row0 = by * 128 + warp_m * 64 + am * 16 + (lid >> 2);
#pragma unroll
            for (int half = 0; half < 2; ++half) {
                int row = row0 + half * 8;
                float y0 = acc[am][bn][half * 2 + 0];
                float y1 = acc[am][bn][half * 2 + 1];
                *(float2*)&g_Y[(size_t)row * N_ + col] = make_float2(y0, y1);
                if (fabsf(y0 + t1a) < DELTA || fabsf(y0 + t2a) < DELTA) {
                    unsigned idx = atomicAdd(&g_nfix, 1u);
                    if (idx < FIXCAP) g_fix[idx] = ((unsigned)row << 13) | (unsigned)col;
                }
                if (fabsf(y1 + t1b) < DELTA || fabsf(y1 + t2b) < DELTA) {
                    unsigned idx = atomicAdd(&g_nfix, 1u);
                    if (idx < FIXCAP) g_fix[idx] = ((unsigned)row << 13) | (unsigned)(col + 1);
                }
            }
        }
    }
}

// ---------------------------------------------------------------------------
// Exact fp64 recompute of flagged gates (one warp per entry, grid-stride)
// ---------------------------------------------------------------------------
__global__ void fixup_kernel(const float* __restrict__ W) {
    int gw = (blockIdx.x * blockDim.x + threadIdx.x) >> 5;
    int lid = threadIdx.x & 31;
    int nwarps = (gridDim.x * blockDim.x) >> 5;
    unsigned n = g_nfix;
    if (n > FIXCAP) n = FIXCAP;
    for (unsigned e = gw; e < n; e += nwarps) {
        unsigned ent = g_fix[e];
        int m = ent >> 13;
        int c = ent & 0x1FFF;
        const float* xr = g_Xf + (size_t)m * K_;
        const float* wr = W + (size_t)c * K_;
        double s = 0.0;
#pragma unroll
        for (int i = 0; i < 16; ++i) {
            int k = (i * 32 + lid) * 4;
            float4 x = *(const float4*)(xr + k);
            float4 w = *(const float4*)(wr + k);
            s += (double)x.x * w.x + (double)x.y * w.y
               + (double)x.z * w.z + (double)x.w * w.w;
        }
#pragma unroll
        for (int off = 16; off > 0; off >>= 1)
            s += __shfl_down_sync(0xFFFFFFFFu, s, off);
        if (lid == 0) g_Y[(size_t)m * N_ + c] = (float)s;
    }
}

// ---------------------------------------------------------------------------
// Gates + LIF
// ---------------------------------------------------------------------------
__global__ void lif_kernel(const float* __restrict__ bih,
                           const float* __restrict__ bhh,
                           float* __restrict__ out) {
    int idx = blockIdx.x * blockDim.x + threadIdx.x;   // over B*H
    if (idx >= B_ * H_) return;
    int b = idx / H_;
    int j = idx - b * H_;

    float bihr = bih[j], bihz = bih[j + H_], bihn = bih[j + 2 * H_];
    float bhhr = bhh[j], bhhz = bhh[j + H_], bhhn = bhh[j + 2 * H_];

    float mem = 0.0f;
    float4 spk4;
    float* sp = &spk4.x;

#pragma unroll
    for (int t = 0; t < T_; t++) {
        const float* yrow = g_Y + (size_t)(b * T_ + t) * N_;
        float gr = (yrow[j] + bihr) + bhhr;
        float gz = (yrow[j + H_] + bihz) + bhhz;
        float r  = gr > 0.0f ? 1.0f : 0.0f;
        float gn = (yrow[j + 2 * H_] + bihn) + r * bhhn;
        float z  = gz > 0.0f ? 1.0f : 0.0f;
        float n  = gn > 0.0f ? 1.0f : 0.0f;
        float h  = (1.0f - z) * n;

        float reset = (mem - 1.0f) > 0.0f ? 1.0f : 0.0f;
        mem = 0.99f * mem + h - reset * 1.0f;
        sp[t] = (mem - 1.0f) > 0.0f ? 1.0f : 0.0f;
    }

    *(float4*)(out + (size_t)idx * T_) = spk4;
}

// ---------------------------------------------------------------------------
extern "C" void kernel_launch(void* const* d_in, const int* in_sizes, int n_in,
                              void* d_out, int out_size) {
    const float* inp = (const float*)d_in[0];   // inputs [B, I, T]
    const float* Wih = (const float*)d_in[1];   // [3H, I]
    const float* bih = (const float*)d_in[2];   // [3H]
    // d_in[3] = W_hh unused (h0 == 0)
    const float* bhh = (const float*)d_in[4];   // [3H]
    float* out = (float*)d_out;                 // [B, H, T]

    cudaFuncSetAttribute(gemm_kernel, cudaFuncAttributeMaxDynamicSharedMemorySize,
                         SMEM_TOTAL);

    zero_fix_kernel<<<1, 1>>>();
    prep_A<<<(B_ * I_ + 255) / 256, 256>>>(inp);
    prep_B<<<(N_ * K_ / 4 + 255) / 256, 256>>>(Wih);

    dim3 grid(N_ / 128, M_ / 128);   // (48, 64)
    gemm_kernel<<<grid, 256, SMEM_TOTAL>>>(bih, bhh);

    fixup_kernel<<<128, 256>>>(Wih);
    lif_kernel<<<(B_ * H_ + 255) / 256, 256>>>(bih, bhh, out);
}